// round 13
// baseline (speedup 1.0000x reference)
#include <cuda_runtime.h>
#include <cuda_fp16.h>
#include <cstdint>

// ----------------------------------------------------------------------------
// InstantNGP hash encode (16 levels, 2^19 tables) + 32->64->64->64->16 MLP.
// MLP on base-ISA tensor cores: mma.sync.m16n8k16 (HMMA) with dual-fp16
// (hi/lo) 3-term products. Activations are pre-scaled by 2^12 before the
// hi/lo split (they are ~1e-4; unscaled, the lo residual falls below fp16's
// subnormal floor and the split degrades to ~6e-4 relative -> R12's 1.7e-3).
// The fp32 accumulator is descaled by 2^-12 (exact) in each epilogue.
// Each warp owns 32 points; no inter-warp barriers after the B-tile load.
// ----------------------------------------------------------------------------

#define NUM_LEVEL 16
#define LOG_T 19
#define TABLE_SIZE (1u << LOG_T)
#define TABLE_MASK (TABLE_SIZE - 1u)

#define TPB 256            // 8 warps, 256 points per block

#define ACT_SCALE   4096.0f          // 2^12
#define ACT_DESCALE (1.0f / 4096.0f)

// ---- bias layout (floats) ----
#define OFF_BIN   0
#define OFF_BH0   64
#define OFF_BH1   128
#define OFF_BOUT  192
#define B_TOTAL   208

__device__ float g_bias[B_TOTAL];
__device__ int   g_tab_mode;       // 0 = half2, 1 = float2, 2 = bf16x2
__constant__ __align__(16) float c_bias[B_TOTAL];

// ---- dual-half swizzled B tiles in global (filled by prep) ----
// B1 (w_in  [64n][32k], 64B pitch, SW64):  HI 0,     LO 4096
// B2 (w_h0  [64n][64k], 128B pitch):       HI 8192,  LO 16384
// B3 (w_h1  [64n][64k], 128B pitch):       HI 24576, LO 32768
// B4 (w_out [16n][64k], 128B pitch):       HI 40960, LO 43008
#define BT_B1HI 0
#define BT_B1LO 4096
#define BT_B2HI 8192
#define BT_B2LO 16384
#define BT_B3HI 24576
#define BT_B3LO 32768
#define BT_B4HI 40960
#define BT_B4LO 43008
#define BT_TOTAL 45056

__device__ __align__(16) char g_Btiles[BT_TOTAL];

// ---- SMEM map (bytes): per-warp A slabs then B tiles ----
#define SMEM_A     0                  // 8 warps x (AHI 4096 + ALO 4096) = 65536
#define WARP_SLAB  8192
#define SMEM_BT    65536              // 45056
#define SMEM_TOTAL 110592

// ============================================================ helpers
__device__ __forceinline__ uint32_t smem_u32(const void* p) {
    uint32_t a;
    asm("{ .reg .u64 t; cvta.to.shared.u64 t, %1; cvt.u32.u64 %0, t; }"
        : "=r"(a) : "l"(p));
    return a;
}
__device__ __forceinline__ uint32_t sw128(uint32_t off) {   // 128B-pitch rows
    return off ^ ((off >> 3) & 0x70);
}
__device__ __forceinline__ uint32_t sw64(uint32_t off) {    // 64B-pitch rows
    return off ^ ((off >> 2) & 0x30);
}
__device__ __forceinline__ void ldsm_x4(uint32_t* r, uint32_t a) {
    asm volatile("ldmatrix.sync.aligned.m8n8.x4.shared.b16 {%0,%1,%2,%3}, [%4];"
                 : "=r"(r[0]), "=r"(r[1]), "=r"(r[2]), "=r"(r[3]) : "r"(a));
}
__device__ __forceinline__ void ldsm_x2(uint32_t* r, uint32_t a) {
    asm volatile("ldmatrix.sync.aligned.m8n8.x2.shared.b16 {%0,%1}, [%2];"
                 : "=r"(r[0]), "=r"(r[1]) : "r"(a));
}
__device__ __forceinline__ void mma16816(float* c, const uint32_t* a,
                                         const uint32_t* b) {
    asm volatile(
        "mma.sync.aligned.m16n8k16.row.col.f32.f16.f16.f32 "
        "{%0,%1,%2,%3}, {%4,%5,%6,%7}, {%8,%9}, {%0,%1,%2,%3};"
        : "+f"(c[0]), "+f"(c[1]), "+f"(c[2]), "+f"(c[3])
        : "r"(a[0]), "r"(a[1]), "r"(a[2]), "r"(a[3]), "r"(b[0]), "r"(b[1]));
}
__device__ __forceinline__ void sts32(uint32_t a, uint32_t v) {
    asm volatile("st.shared.b32 [%0], %1;" :: "r"(a), "r"(v) : "memory");
}
__device__ __forceinline__ void sts128(uint32_t a, uint4 v) {
    asm volatile("st.shared.v4.b32 [%0], {%1,%2,%3,%4};"
                 :: "r"(a), "r"(v.x), "r"(v.y), "r"(v.z), "r"(v.w) : "memory");
}
// Split v (already scaled) into hi/lo fp16 pair words.
__device__ __forceinline__ uint32_t pack_hilo(float v0, float v1, uint32_t& lo_out) {
    __half h0 = __float2half_rn(v0);
    __half h1 = __float2half_rn(v1);
    __half l0 = __float2half_rn(v0 - __half2float(h0));
    __half l1 = __float2half_rn(v1 - __half2float(h1));
    __half2 hp = __halves2half2(h0, h1);
    __half2 lp = __halves2half2(l0, l1);
    lo_out = *(uint32_t*)&lp;
    return *(uint32_t*)&hp;
}

// ------------------------------------------------- prep (+ probe + B tiles)
__device__ __forceinline__ void put_b128(int bhi, int blo, int n, int k, float v) {
    __half h = __float2half_rn(v);
    __half l = __float2half_rn(v - __half2float(h));
    uint32_t sw = sw128((uint32_t)(n * 128 + k * 2));
    *(__half*)(g_Btiles + bhi + sw) = h;
    *(__half*)(g_Btiles + blo + sw) = l;
}
__device__ __forceinline__ void put_b64(int bhi, int blo, int n, int k, float v) {
    __half h = __float2half_rn(v);
    __half l = __float2half_rn(v - __half2float(h));
    uint32_t sw = sw64((uint32_t)(n * 64 + k * 2));
    *(__half*)(g_Btiles + bhi + sw) = h;
    *(__half*)(g_Btiles + blo + sw) = l;
}

__global__ void prep_weights_kernel(
    const float* __restrict__ w_in, const float* __restrict__ b_in,
    const float* __restrict__ w_h0, const float* __restrict__ b_h0,
    const float* __restrict__ w_h1, const float* __restrict__ b_h1,
    const float* __restrict__ w_out, const float* __restrict__ b_out,
    const unsigned int* __restrict__ tab) {
    int t = blockIdx.x * blockDim.x + threadIdx.x;
    int stride = gridDim.x * blockDim.x;

    if (blockIdx.x == 0 && threadIdx.x < 32) {
        int tiny = 0, lowband = 0;
        for (int i = 0; i < 8; i++) {
            unsigned int w = tab[(threadIdx.x * 8 + i) * 97 + 1];
            float fh = __uint_as_float(w);
            float fl = __uint_as_float(w << 16);
            if (fabsf(fh) < 1e-20f) tiny++;
            float al = fabsf(fl);
            if (al > 1e-6f && al < 1e-2f) lowband++;
        }
        tiny    = __reduce_add_sync(0xFFFFFFFFu, tiny);
        lowband = __reduce_add_sync(0xFFFFFFFFu, lowband);
        if (threadIdx.x == 0)
            g_tab_mode = (tiny > 128) ? 0 : ((lowband > 128) ? 2 : 1);
    }

    for (int k = t; k < 64; k += stride) g_bias[OFF_BIN + k] = b_in[k];
    for (int k = t; k < 64; k += stride) g_bias[OFF_BH0 + k] = b_h0[k];
    for (int k = t; k < 64; k += stride) g_bias[OFF_BH1 + k] = b_h1[k];
    for (int k = t; k < 16; k += stride) g_bias[OFF_BOUT + k] = b_out[k];

    for (int i = t; i < 64 * 32; i += stride)       // layer1 [64][32]
        put_b64(BT_B1HI, BT_B1LO, i >> 5, i & 31, w_in[i]);
    for (int i = t; i < 64 * 64; i += stride)       // h0
        put_b128(BT_B2HI, BT_B2LO, i >> 6, i & 63, w_h0[i]);
    for (int i = t; i < 64 * 64; i += stride)       // h1
        put_b128(BT_B3HI, BT_B3LO, i >> 6, i & 63, w_h1[i]);
    for (int i = t; i < 16 * 64; i += stride)       // out
        put_b128(BT_B4HI, BT_B4LO, i >> 6, i & 63, w_out[i]);
}

// ---------------------------------------------------------------- table fetch
template <int MODE>
__device__ __forceinline__ float2 tab_fetch(const void* __restrict__ base,
                                            unsigned idx) {
    if (MODE == 0) {
        __half2 v = __ldg(((const __half2*)base) + idx);
        return __half22float2(v);
    } else if (MODE == 1) {
        return __ldg(((const float2*)base) + idx);
    } else {
        unsigned int w = __ldg(((const unsigned int*)base) + idx);
        return make_float2(__uint_as_float(w << 16),
                           __uint_as_float(w & 0xFFFF0000u));
    }
}

struct LevelSetup {
    unsigned hx0, hx1, hy0, hy1, hz0, hz1;
    float ax, ay, az, bx, by, bz;      // floor-frac (a*), ceil-frac (b*)
};
__device__ __forceinline__ LevelSetup level_setup(float cx, float cy, float cz,
                                                  float r) {
    LevelSetup s;
    float sx = cx * r, sy = cy * r, sz = cz * r;
    float fx = floorf(sx), fy = floorf(sy), fz = floorf(sz);
    float gx = ceilf(sx), gy = ceilf(sy), gz = ceilf(sz);
    s.ax = sx - fx; s.ay = sy - fy; s.az = sz - fz;
    s.bx = gx - sx; s.by = gy - sy; s.bz = gz - sz;
    s.hx0 = (unsigned)(int)fx;
    s.hx1 = (unsigned)(int)gx;
    s.hy0 = (unsigned)(int)fy * 2654435761u;
    s.hy1 = (unsigned)(int)gy * 2654435761u;
    s.hz0 = (unsigned)(int)fz * 805459861u;
    s.hz1 = (unsigned)(int)gz * 805459861u;
    return s;
}
__device__ __forceinline__ unsigned corner_hash(const LevelSetup& s, int o) {
    return (((o & 4) ? s.hx1 : s.hx0) ^ ((o & 2) ? s.hy1 : s.hy0) ^
            ((o & 1) ? s.hz1 : s.hz0)) & TABLE_MASK;
}
__device__ __forceinline__ float corner_w(const LevelSetup& s, int o) {
    return ((o & 4) ? s.ax : s.bx) * ((o & 2) ? s.ay : s.by) *
           ((o & 1) ? s.az : s.bz);
}

// ----------------------- encode 1 point -> row `lane` of warp A slab (hi/lo)
template <int MODE>
__device__ __forceinline__ void encode_to_A(
    const char* __restrict__ tables, float cx, float cy, float cz,
    uint32_t slab_hi, uint32_t slab_lo, int lane) {
    const float RES[NUM_LEVEL] = {16.f, 20.f, 25.f, 32.f, 40.f, 50.f, 64.f, 80.f,
                                  101.f, 128.f, 161.f, 203.f, 256.f, 322.f, 406.f, 512.f};
    const int ELEM_BYTES = (MODE == 1) ? 8 : 4;

    uint32_t uh[16], ul[16];
#pragma unroll
    for (int lp = 0; lp < 8; lp++) {            // 2 levels per batch
        int l0 = 2 * lp, l1 = 2 * lp + 1;
        LevelSetup s0 = level_setup(cx, cy, cz, RES[l0]);
        LevelSetup s1 = level_setup(cx, cy, cz, RES[l1]);
        const void* t0 = tables + (size_t)l0 * TABLE_SIZE * ELEM_BYTES;
        const void* t1 = tables + (size_t)l1 * TABLE_SIZE * ELEM_BYTES;

        float2 f0[8], f1[8];                    // 16 gathers in flight
#pragma unroll
        for (int o = 0; o < 8; o++) f0[o] = tab_fetch<MODE>(t0, corner_hash(s0, o));
#pragma unroll
        for (int o = 0; o < 8; o++) f1[o] = tab_fetch<MODE>(t1, corner_hash(s1, o));

        float a0 = 0.f, a1 = 0.f, b0 = 0.f, b1 = 0.f;
#pragma unroll
        for (int o = 0; o < 8; o++) {
            float w0 = corner_w(s0, o), w1 = corner_w(s1, o);
            a0 = fmaf(f0[o].x, w0, a0);
            a1 = fmaf(f0[o].y, w0, a1);
            b0 = fmaf(f1[o].x, w1, b0);
            b1 = fmaf(f1[o].y, w1, b1);
        }
        // scale by 2^12 before the split (keeps lo out of subnormal range)
        uh[l0] = pack_hilo(a0 * ACT_SCALE, a1 * ACT_SCALE, ul[l0]);
        uh[l1] = pack_hilo(b0 * ACT_SCALE, b1 * ACT_SCALE, ul[l1]);
    }
#pragma unroll
    for (int q = 0; q < 4; q++) {
        uint32_t sw = sw128((uint32_t)(lane * 128 + q * 16));
        sts128(slab_hi + sw, make_uint4(uh[4*q], uh[4*q+1], uh[4*q+2], uh[4*q+3]));
        sts128(slab_lo + sw, make_uint4(ul[4*q], ul[4*q+1], ul[4*q+2], ul[4*q+3]));
    }
}

// ------------------------------------------- one MMA layer (dual-half, 3-term)
template <int KSTEPS, int NTILES, bool B64>
__device__ __forceinline__ void run_layer(
    uint32_t slab_hi, uint32_t slab_lo, uint32_t b_hi, uint32_t b_lo,
    int lane, float acc[2][8][4]) {
#pragma unroll
    for (int mt = 0; mt < 2; mt++)
#pragma unroll
        for (int nt = 0; nt < NTILES; nt++)
#pragma unroll
            for (int i = 0; i < 4; i++) acc[mt][nt][i] = 0.0f;

    uint32_t rA = (uint32_t)(lane & 15);
    uint32_t cA = (uint32_t)((lane >> 4) << 4);   // 0 or 16 bytes
    uint32_t rB = (uint32_t)(lane & 7);
    uint32_t cB = (uint32_t)(((lane >> 3) & 1) << 4);

#pragma unroll
    for (int ks = 0; ks < KSTEPS; ks++) {
        uint32_t ah[2][4], al[2][4];
#pragma unroll
        for (int mt = 0; mt < 2; mt++) {
            uint32_t off = sw128((mt * 16 + rA) * 128 + ks * 32 + cA);
            ldsm_x4(ah[mt], slab_hi + off);
            ldsm_x4(al[mt], slab_lo + off);
        }
#pragma unroll
        for (int nt = 0; nt < NTILES; nt++) {
            uint32_t offB = B64 ? sw64((nt * 8 + rB) * 64 + ks * 32 + cB)
                                : sw128((nt * 8 + rB) * 128 + ks * 32 + cB);
            uint32_t bh[2], bl[2];
            ldsm_x2(bh, b_hi + offB);
            ldsm_x2(bl, b_lo + offB);
#pragma unroll
            for (int mt = 0; mt < 2; mt++) {
                mma16816(acc[mt][nt], ah[mt], bh);
                mma16816(acc[mt][nt], al[mt], bh);
                mma16816(acc[mt][nt], ah[mt], bl);
            }
        }
    }
}

// ----------------------------- hidden epilogue: descale, +bias, relu, repack
template <int BOFF>
__device__ __forceinline__ void epi_hidden(float acc[2][8][4],
                                           uint32_t slab_hi, uint32_t slab_lo,
                                           int lane) {
    int g = lane >> 2, id = lane & 3;
    __syncwarp();
#pragma unroll
    for (int mt = 0; mt < 2; mt++)
#pragma unroll
        for (int nt = 0; nt < 8; nt++)
#pragma unroll
            for (int h = 0; h < 2; h++) {
                int col = nt * 8 + 2 * id;
                float v0 = fmaxf(fmaf(acc[mt][nt][2*h],     ACT_DESCALE,
                                      c_bias[BOFF + col]), 0.0f);
                float v1 = fmaxf(fmaf(acc[mt][nt][2*h + 1], ACT_DESCALE,
                                      c_bias[BOFF + col + 1]), 0.0f);
                uint32_t lo, hi = pack_hilo(v0 * ACT_SCALE, v1 * ACT_SCALE, lo);
                uint32_t off = sw128((mt * 16 + g + 8 * h) * 128 + col * 2);
                sts32(slab_hi + off, hi);
                sts32(slab_lo + off, lo);
            }
    __syncwarp();
}

// ---------------------------------------------------------------- main kernel
__global__ __launch_bounds__(TPB, 2) void nerf_mma_kernel(
    const float* __restrict__ coords,
    const char* __restrict__ tables,
    float* __restrict__ out) {
    extern __shared__ char sm[];
    uint32_t smem_base = smem_u32(sm);
    int tid = threadIdx.x;
    int w = tid >> 5;
    int lane = tid & 31;

    // Cooperative B-tile load (only block-wide sync in the kernel)
    {
        const uint4* src = (const uint4*)g_Btiles;
        uint4* dst = (uint4*)(sm + SMEM_BT);
        for (int k = tid; k < BT_TOTAL / 16; k += TPB) dst[k] = src[k];
    }
    __syncthreads();

    uint32_t slab_hi = smem_base + SMEM_A + w * WARP_SLAB;
    uint32_t slab_lo = slab_hi + 4096;
    uint32_t bt = smem_base + SMEM_BT;

    int p = blockIdx.x * TPB + tid;
    float cx = coords[3 * p + 0];
    float cy = coords[3 * p + 1];
    float cz = coords[3 * p + 2];

    int mode = g_tab_mode;
    if (mode == 1)      encode_to_A<1>(tables, cx, cy, cz, slab_hi, slab_lo, lane);
    else if (mode == 0) encode_to_A<0>(tables, cx, cy, cz, slab_hi, slab_lo, lane);
    else                encode_to_A<2>(tables, cx, cy, cz, slab_hi, slab_lo, lane);
    __syncwarp();

    float acc[2][8][4];

    // layer 1: K=32 (2 ksteps), N=64, B at 64B pitch
    run_layer<2, 8, true>(slab_hi, slab_lo, bt + BT_B1HI, bt + BT_B1LO, lane, acc);
    epi_hidden<OFF_BIN>(acc, slab_hi, slab_lo, lane);

    // h0: K=64, N=64
    run_layer<4, 8, false>(slab_hi, slab_lo, bt + BT_B2HI, bt + BT_B2LO, lane, acc);
    epi_hidden<OFF_BH0>(acc, slab_hi, slab_lo, lane);

    // h1: K=64, N=64
    run_layer<4, 8, false>(slab_hi, slab_lo, bt + BT_B3HI, bt + BT_B3LO, lane, acc);
    epi_hidden<OFF_BH1>(acc, slab_hi, slab_lo, lane);

    // out: K=64, N=16 (2 ntiles), descale + bias, straight to global
    run_layer<4, 2, false>(slab_hi, slab_lo, bt + BT_B4HI, bt + BT_B4LO, lane, acc);
    {
        int g = lane >> 2, id = lane & 3;
        int pbase = blockIdx.x * TPB + w * 32;
#pragma unroll
        for (int mt = 0; mt < 2; mt++)
#pragma unroll
            for (int nt = 0; nt < 2; nt++)
#pragma unroll
                for (int h = 0; h < 2; h++) {
                    int col = nt * 8 + 2 * id;
                    int row = mt * 16 + g + 8 * h;
                    float v0 = fmaf(acc[mt][nt][2*h],     ACT_DESCALE,
                                    c_bias[OFF_BOUT + col]);
                    float v1 = fmaf(acc[mt][nt][2*h + 1], ACT_DESCALE,
                                    c_bias[OFF_BOUT + col + 1]);
                    *(float2*)(out + (size_t)(pbase + row) * 16 + col) =
                        make_float2(v0, v1);
                }
    }
}

// ---------------------------------------------------------------- launch
extern "C" void kernel_launch(void* const* d_in, const int* in_sizes, int n_in,
                              void* d_out, int out_size) {
    const float* coords = (const float*)d_in[0];
    const char* tables  = (const char*)d_in[1];
    const float* w_in  = (const float*)d_in[2];
    const float* b_in  = (const float*)d_in[3];
    const float* w_h0  = (const float*)d_in[4];
    const float* b_h0  = (const float*)d_in[5];
    const float* w_h1  = (const float*)d_in[6];
    const float* b_h1  = (const float*)d_in[7];
    const float* w_out = (const float*)d_in[8];
    const float* b_out = (const float*)d_in[9];
    float* out = (float*)d_out;

    int n = in_sizes[0] / 3;

    prep_weights_kernel<<<32, 256>>>(w_in, b_in, w_h0, b_h0, w_h1, b_h1,
                                     w_out, b_out, (const unsigned int*)tables);

    void* g_addr = nullptr;
    cudaGetSymbolAddress(&g_addr, g_bias);
    cudaMemcpyToSymbolAsync(c_bias, g_addr, B_TOTAL * sizeof(float), 0,
                            cudaMemcpyDeviceToDevice);

    cudaFuncSetAttribute(nerf_mma_kernel,
                         cudaFuncAttributeMaxDynamicSharedMemorySize, SMEM_TOTAL);
    nerf_mma_kernel<<<n / TPB, TPB, SMEM_TOTAL>>>(coords, tables, out);
}

// round 15
// speedup vs baseline: 1.5483x; 1.5483x over previous
#include <cuda_runtime.h>
#include <cuda_fp16.h>
#include <cstdint>

// ----------------------------------------------------------------------------
// InstantNGP hash encode + 32->64->64->64->16 MLP, SPLIT into two kernels:
//  1) encode_kernel: no smem, 24 warps/SM, writes scaled hi/lo fp16 feature
//     words to a transposed global buffer (coalesced).
//  2) mlp_kernel: HMMA (m16n8k16) dual-fp16 3-term layers per 32-point warp
//     tile (proven in R13), loading features coalesced from the buffer.
// Splitting decouples occupancy needs: encode is latency-bound (wants warps),
// MLP is tensor-bound (wants smem).
// ----------------------------------------------------------------------------

#define NUM_LEVEL 16
#define LOG_T 19
#define TABLE_SIZE (1u << LOG_T)
#define TABLE_MASK (TABLE_SIZE - 1u)

#define TPB 256
#define NMAX 262144                  // max points (fixed problem size)

#define ACT_SCALE   4096.0f          // 2^12
#define ACT_DESCALE (1.0f / 4096.0f)

// ---- bias layout (floats) ----
#define OFF_BIN   0
#define OFF_BH0   64
#define OFF_BH1   128
#define OFF_BOUT  192
#define B_TOTAL   208

__device__ float g_bias[B_TOTAL];
__device__ int   g_tab_mode;       // 0 = half2, 1 = float2, 2 = bf16x2
__constant__ __align__(16) float c_bias[B_TOTAL];

// Feature buffer: [q][point], q = feature-pair index (0..15).
// .x = hi fp16x2 word, .y = lo fp16x2 word (activations pre-scaled by 2^12).
__device__ __align__(16) uint2 g_feat[16 * NMAX];

// ---- dual-half swizzled B tiles in global (filled by prep) ----
#define BT_B1HI 0
#define BT_B1LO 4096
#define BT_B2HI 8192
#define BT_B2LO 16384
#define BT_B3HI 24576
#define BT_B3LO 32768
#define BT_B4HI 40960
#define BT_B4LO 43008
#define BT_TOTAL 45056

__device__ __align__(16) char g_Btiles[BT_TOTAL];

// ---- MLP kernel SMEM map: per-warp A slabs then B tiles ----
#define SMEM_A     0                  // 8 warps x (AHI 4096 + ALO 4096)
#define WARP_SLAB  8192
#define SMEM_BT    65536
#define SMEM_TOTAL 110592

// ============================================================ helpers
__device__ __forceinline__ uint32_t smem_u32(const void* p) {
    uint32_t a;
    asm("{ .reg .u64 t; cvta.to.shared.u64 t, %1; cvt.u32.u64 %0, t; }"
        : "=r"(a) : "l"(p));
    return a;
}
__device__ __forceinline__ uint32_t sw128(uint32_t off) {   // 128B-pitch rows
    return off ^ ((off >> 3) & 0x70);
}
__device__ __forceinline__ uint32_t sw64(uint32_t off) {    // 64B-pitch rows
    return off ^ ((off >> 2) & 0x30);
}
__device__ __forceinline__ void ldsm_x4(uint32_t* r, uint32_t a) {
    asm volatile("ldmatrix.sync.aligned.m8n8.x4.shared.b16 {%0,%1,%2,%3}, [%4];"
                 : "=r"(r[0]), "=r"(r[1]), "=r"(r[2]), "=r"(r[3]) : "r"(a));
}
__device__ __forceinline__ void ldsm_x2(uint32_t* r, uint32_t a) {
    asm volatile("ldmatrix.sync.aligned.m8n8.x2.shared.b16 {%0,%1}, [%2];"
                 : "=r"(r[0]), "=r"(r[1]) : "r"(a));
}
__device__ __forceinline__ void mma16816(float* c, const uint32_t* a,
                                         const uint32_t* b) {
    asm volatile(
        "mma.sync.aligned.m16n8k16.row.col.f32.f16.f16.f32 "
        "{%0,%1,%2,%3}, {%4,%5,%6,%7}, {%8,%9}, {%0,%1,%2,%3};"
        : "+f"(c[0]), "+f"(c[1]), "+f"(c[2]), "+f"(c[3])
        : "r"(a[0]), "r"(a[1]), "r"(a[2]), "r"(a[3]), "r"(b[0]), "r"(b[1]));
}
__device__ __forceinline__ void sts32(uint32_t a, uint32_t v) {
    asm volatile("st.shared.b32 [%0], %1;" :: "r"(a), "r"(v) : "memory");
}
__device__ __forceinline__ void sts128(uint32_t a, uint4 v) {
    asm volatile("st.shared.v4.b32 [%0], {%1,%2,%3,%4};"
                 :: "r"(a), "r"(v.x), "r"(v.y), "r"(v.z), "r"(v.w) : "memory");
}
__device__ __forceinline__ uint32_t pack_hilo(float v0, float v1, uint32_t& lo_out) {
    __half h0 = __float2half_rn(v0);
    __half h1 = __float2half_rn(v1);
    __half l0 = __float2half_rn(v0 - __half2float(h0));
    __half l1 = __float2half_rn(v1 - __half2float(h1));
    __half2 hp = __halves2half2(h0, h1);
    __half2 lp = __halves2half2(l0, l1);
    lo_out = *(uint32_t*)&lp;
    return *(uint32_t*)&hp;
}

// ------------------------------------------------- prep (+ probe + B tiles)
__device__ __forceinline__ void put_b128(int bhi, int blo, int n, int k, float v) {
    __half h = __float2half_rn(v);
    __half l = __float2half_rn(v - __half2float(h));
    uint32_t sw = sw128((uint32_t)(n * 128 + k * 2));
    *(__half*)(g_Btiles + bhi + sw) = h;
    *(__half*)(g_Btiles + blo + sw) = l;
}
__device__ __forceinline__ void put_b64(int bhi, int blo, int n, int k, float v) {
    __half h = __float2half_rn(v);
    __half l = __float2half_rn(v - __half2float(h));
    uint32_t sw = sw64((uint32_t)(n * 64 + k * 2));
    *(__half*)(g_Btiles + bhi + sw) = h;
    *(__half*)(g_Btiles + blo + sw) = l;
}

__global__ void prep_weights_kernel(
    const float* __restrict__ w_in, const float* __restrict__ b_in,
    const float* __restrict__ w_h0, const float* __restrict__ b_h0,
    const float* __restrict__ w_h1, const float* __restrict__ b_h1,
    const float* __restrict__ w_out, const float* __restrict__ b_out,
    const unsigned int* __restrict__ tab) {
    int t = blockIdx.x * blockDim.x + threadIdx.x;
    int stride = gridDim.x * blockDim.x;

    if (blockIdx.x == 0 && threadIdx.x < 32) {
        int tiny = 0, lowband = 0;
        for (int i = 0; i < 8; i++) {
            unsigned int w = tab[(threadIdx.x * 8 + i) * 97 + 1];
            float fh = __uint_as_float(w);
            float fl = __uint_as_float(w << 16);
            if (fabsf(fh) < 1e-20f) tiny++;
            float al = fabsf(fl);
            if (al > 1e-6f && al < 1e-2f) lowband++;
        }
        tiny    = __reduce_add_sync(0xFFFFFFFFu, tiny);
        lowband = __reduce_add_sync(0xFFFFFFFFu, lowband);
        if (threadIdx.x == 0)
            g_tab_mode = (tiny > 128) ? 0 : ((lowband > 128) ? 2 : 1);
    }

    for (int k = t; k < 64; k += stride) g_bias[OFF_BIN + k] = b_in[k];
    for (int k = t; k < 64; k += stride) g_bias[OFF_BH0 + k] = b_h0[k];
    for (int k = t; k < 64; k += stride) g_bias[OFF_BH1 + k] = b_h1[k];
    for (int k = t; k < 16; k += stride) g_bias[OFF_BOUT + k] = b_out[k];

    for (int i = t; i < 64 * 32; i += stride)       // layer1 [64][32]
        put_b64(BT_B1HI, BT_B1LO, i >> 5, i & 31, w_in[i]);
    for (int i = t; i < 64 * 64; i += stride)       // h0
        put_b128(BT_B2HI, BT_B2LO, i >> 6, i & 63, w_h0[i]);
    for (int i = t; i < 64 * 64; i += stride)       // h1
        put_b128(BT_B3HI, BT_B3LO, i >> 6, i & 63, w_h1[i]);
    for (int i = t; i < 16 * 64; i += stride)       // out
        put_b128(BT_B4HI, BT_B4LO, i >> 6, i & 63, w_out[i]);
}

// ---------------------------------------------------------------- table fetch
template <int MODE>
__device__ __forceinline__ float2 tab_fetch(const void* __restrict__ base,
                                            unsigned idx) {
    if (MODE == 0) {
        __half2 v = __ldg(((const __half2*)base) + idx);
        return __half22float2(v);
    } else if (MODE == 1) {
        return __ldg(((const float2*)base) + idx);
    } else {
        unsigned int w = __ldg(((const unsigned int*)base) + idx);
        return make_float2(__uint_as_float(w << 16),
                           __uint_as_float(w & 0xFFFF0000u));
    }
}

struct LevelSetup {
    unsigned hx0, hx1, hy0, hy1, hz0, hz1;
    float ax, ay, az, bx, by, bz;
};
__device__ __forceinline__ LevelSetup level_setup(float cx, float cy, float cz,
                                                  float r) {
    LevelSetup s;
    float sx = cx * r, sy = cy * r, sz = cz * r;
    float fx = floorf(sx), fy = floorf(sy), fz = floorf(sz);
    float gx = ceilf(sx), gy = ceilf(sy), gz = ceilf(sz);
    s.ax = sx - fx; s.ay = sy - fy; s.az = sz - fz;
    s.bx = gx - sx; s.by = gy - sy; s.bz = gz - sz;
    s.hx0 = (unsigned)(int)fx;
    s.hx1 = (unsigned)(int)gx;
    s.hy0 = (unsigned)(int)fy * 2654435761u;
    s.hy1 = (unsigned)(int)gy * 2654435761u;
    s.hz0 = (unsigned)(int)fz * 805459861u;
    s.hz1 = (unsigned)(int)gz * 805459861u;
    return s;
}
__device__ __forceinline__ unsigned corner_hash(const LevelSetup& s, int o) {
    return (((o & 4) ? s.hx1 : s.hx0) ^ ((o & 2) ? s.hy1 : s.hy0) ^
            ((o & 1) ? s.hz1 : s.hz0)) & TABLE_MASK;
}
__device__ __forceinline__ float corner_w(const LevelSetup& s, int o) {
    return ((o & 4) ? s.ax : s.bx) * ((o & 2) ? s.ay : s.by) *
           ((o & 1) ? s.az : s.bz);
}

// ======================================================= KERNEL 1: encode
template <int MODE>
__device__ __forceinline__ void encode_point(
    const char* __restrict__ tables, float cx, float cy, float cz, int p) {
    const float RES[NUM_LEVEL] = {16.f, 20.f, 25.f, 32.f, 40.f, 50.f, 64.f, 80.f,
                                  101.f, 128.f, 161.f, 203.f, 256.f, 322.f, 406.f, 512.f};
    const int ELEM_BYTES = (MODE == 1) ? 8 : 4;

#pragma unroll
    for (int lp = 0; lp < 8; lp++) {            // 2 levels per batch
        int l0 = 2 * lp, l1 = 2 * lp + 1;
        LevelSetup s0 = level_setup(cx, cy, cz, RES[l0]);
        LevelSetup s1 = level_setup(cx, cy, cz, RES[l1]);
        const void* t0 = tables + (size_t)l0 * TABLE_SIZE * ELEM_BYTES;
        const void* t1 = tables + (size_t)l1 * TABLE_SIZE * ELEM_BYTES;

        float2 f0[8], f1[8];                    // 16 gathers in flight
#pragma unroll
        for (int o = 0; o < 8; o++) f0[o] = tab_fetch<MODE>(t0, corner_hash(s0, o));
#pragma unroll
        for (int o = 0; o < 8; o++) f1[o] = tab_fetch<MODE>(t1, corner_hash(s1, o));

        float a0 = 0.f, a1 = 0.f, b0 = 0.f, b1 = 0.f;
#pragma unroll
        for (int o = 0; o < 8; o++) {
            float w0 = corner_w(s0, o), w1 = corner_w(s1, o);
            a0 = fmaf(f0[o].x, w0, a0);
            a1 = fmaf(f0[o].y, w0, a1);
            b0 = fmaf(f1[o].x, w1, b0);
            b1 = fmaf(f1[o].y, w1, b1);
        }
        uint32_t lo0, hi0 = pack_hilo(a0 * ACT_SCALE, a1 * ACT_SCALE, lo0);
        uint32_t lo1, hi1 = pack_hilo(b0 * ACT_SCALE, b1 * ACT_SCALE, lo1);
        g_feat[l0 * NMAX + p] = make_uint2(hi0, lo0);   // coalesced STG.64
        g_feat[l1 * NMAX + p] = make_uint2(hi1, lo1);
    }
}

__global__ __launch_bounds__(TPB, 3) void encode_kernel(
    const float* __restrict__ coords,
    const char* __restrict__ tables) {
    int p = blockIdx.x * TPB + threadIdx.x;
    float cx = coords[3 * p + 0];
    float cy = coords[3 * p + 1];
    float cz = coords[3 * p + 2];
    int mode = g_tab_mode;
    if (mode == 1)      encode_point<1>(tables, cx, cy, cz, p);
    else if (mode == 0) encode_point<0>(tables, cx, cy, cz, p);
    else                encode_point<2>(tables, cx, cy, cz, p);
}

// ======================================================= KERNEL 2: MLP
template <int KSTEPS, int NTILES, bool B64>
__device__ __forceinline__ void run_layer(
    uint32_t slab_hi, uint32_t slab_lo, uint32_t b_hi, uint32_t b_lo,
    int lane, float acc[2][8][4]) {
#pragma unroll
    for (int mt = 0; mt < 2; mt++)
#pragma unroll
        for (int nt = 0; nt < NTILES; nt++)
#pragma unroll
            for (int i = 0; i < 4; i++) acc[mt][nt][i] = 0.0f;

    uint32_t rA = (uint32_t)(lane & 15);
    uint32_t cA = (uint32_t)((lane >> 4) << 4);
    uint32_t rB = (uint32_t)(lane & 7);
    uint32_t cB = (uint32_t)(((lane >> 3) & 1) << 4);

#pragma unroll
    for (int ks = 0; ks < KSTEPS; ks++) {
        uint32_t ah[2][4], al[2][4];
#pragma unroll
        for (int mt = 0; mt < 2; mt++) {
            uint32_t off = sw128((mt * 16 + rA) * 128 + ks * 32 + cA);
            ldsm_x4(ah[mt], slab_hi + off);
            ldsm_x4(al[mt], slab_lo + off);
        }
#pragma unroll
        for (int nt = 0; nt < NTILES; nt++) {
            uint32_t offB = B64 ? sw64((nt * 8 + rB) * 64 + ks * 32 + cB)
                                : sw128((nt * 8 + rB) * 128 + ks * 32 + cB);
            uint32_t bh[2], bl[2];
            ldsm_x2(bh, b_hi + offB);
            ldsm_x2(bl, b_lo + offB);
#pragma unroll
            for (int mt = 0; mt < 2; mt++) {
                mma16816(acc[mt][nt], ah[mt], bh);
                mma16816(acc[mt][nt], al[mt], bh);
                mma16816(acc[mt][nt], ah[mt], bl);
            }
        }
    }
}

template <int BOFF>
__device__ __forceinline__ void epi_hidden(float acc[2][8][4],
                                           uint32_t slab_hi, uint32_t slab_lo,
                                           int lane) {
    int g = lane >> 2, id = lane & 3;
    __syncwarp();
#pragma unroll
    for (int mt = 0; mt < 2; mt++)
#pragma unroll
        for (int nt = 0; nt < 8; nt++)
#pragma unroll
            for (int h = 0; h < 2; h++) {
                int col = nt * 8 + 2 * id;
                float v0 = fmaxf(fmaf(acc[mt][nt][2*h],     ACT_DESCALE,
                                      c_bias[BOFF + col]), 0.0f);
                float v1 = fmaxf(fmaf(acc[mt][nt][2*h + 1], ACT_DESCALE,
                                      c_bias[BOFF + col + 1]), 0.0f);
                uint32_t lo, hi = pack_hilo(v0 * ACT_SCALE, v1 * ACT_SCALE, lo);
                uint32_t off = sw128((mt * 16 + g + 8 * h) * 128 + col * 2);
                sts32(slab_hi + off, hi);
                sts32(slab_lo + off, lo);
            }
    __syncwarp();
}

__global__ __launch_bounds__(TPB, 2) void mlp_kernel(float* __restrict__ out) {
    extern __shared__ char sm[];
    uint32_t smem_base = smem_u32(sm);
    int tid = threadIdx.x;
    int w = tid >> 5;
    int lane = tid & 31;

    // Cooperative B-tile load (only block-wide sync in the kernel)
    {
        const uint4* src = (const uint4*)g_Btiles;
        uint4* dst = (uint4*)(sm + SMEM_BT);
        for (int k = tid; k < BT_TOTAL / 16; k += TPB) dst[k] = src[k];
    }
    __syncthreads();

    uint32_t slab_hi = smem_base + SMEM_A + w * WARP_SLAB;
    uint32_t slab_lo = slab_hi + 4096;
    uint32_t bt = smem_base + SMEM_BT;

    // Load this point's 16 feature-pair words (coalesced LDG.64) into A slab.
    int p = blockIdx.x * TPB + tid;
#pragma unroll
    for (int j = 0; j < 4; j++) {
        uint2 v0 = g_feat[(4 * j + 0) * NMAX + p];
        uint2 v1 = g_feat[(4 * j + 1) * NMAX + p];
        uint2 v2 = g_feat[(4 * j + 2) * NMAX + p];
        uint2 v3 = g_feat[(4 * j + 3) * NMAX + p];
        uint32_t sw = sw128((uint32_t)(lane * 128 + j * 16));
        sts128(slab_hi + sw, make_uint4(v0.x, v1.x, v2.x, v3.x));
        sts128(slab_lo + sw, make_uint4(v0.y, v1.y, v2.y, v3.y));
    }
    __syncwarp();

    float acc[2][8][4];

    // layer 1: K=32 (2 ksteps), N=64, B at 64B pitch
    run_layer<2, 8, true>(slab_hi, slab_lo, bt + BT_B1HI, bt + BT_B1LO, lane, acc);
    epi_hidden<OFF_BIN>(acc, slab_hi, slab_lo, lane);

    // h0: K=64, N=64
    run_layer<4, 8, false>(slab_hi, slab_lo, bt + BT_B2HI, bt + BT_B2LO, lane, acc);
    epi_hidden<OFF_BH0>(acc, slab_hi, slab_lo, lane);

    // h1: K=64, N=64
    run_layer<4, 8, false>(slab_hi, slab_lo, bt + BT_B3HI, bt + BT_B3LO, lane, acc);
    epi_hidden<OFF_BH1>(acc, slab_hi, slab_lo, lane);

    // out: K=64, N=16 (2 ntiles), descale + bias, straight to global
    run_layer<4, 2, false>(slab_hi, slab_lo, bt + BT_B4HI, bt + BT_B4LO, lane, acc);
    {
        int g = lane >> 2, id = lane & 3;
        int pbase = blockIdx.x * TPB + w * 32;
#pragma unroll
        for (int mt = 0; mt < 2; mt++)
#pragma unroll
            for (int nt = 0; nt < 2; nt++)
#pragma unroll
                for (int h = 0; h < 2; h++) {
                    int col = nt * 8 + 2 * id;
                    int row = mt * 16 + g + 8 * h;
                    float v0 = fmaf(acc[mt][nt][2*h],     ACT_DESCALE,
                                    c_bias[OFF_BOUT + col]);
                    float v1 = fmaf(acc[mt][nt][2*h + 1], ACT_DESCALE,
                                    c_bias[OFF_BOUT + col + 1]);
                    *(float2*)(out + (size_t)(pbase + row) * 16 + col) =
                        make_float2(v0, v1);
                }
    }
}

// ---------------------------------------------------------------- launch
extern "C" void kernel_launch(void* const* d_in, const int* in_sizes, int n_in,
                              void* d_out, int out_size) {
    const float* coords = (const float*)d_in[0];
    const char* tables  = (const char*)d_in[1];
    const float* w_in  = (const float*)d_in[2];
    const float* b_in  = (const float*)d_in[3];
    const float* w_h0  = (const float*)d_in[4];
    const float* b_h0  = (const float*)d_in[5];
    const float* w_h1  = (const float*)d_in[6];
    const float* b_h1  = (const float*)d_in[7];
    const float* w_out = (const float*)d_in[8];
    const float* b_out = (const float*)d_in[9];
    float* out = (float*)d_out;

    int n = in_sizes[0] / 3;

    prep_weights_kernel<<<32, 256>>>(w_in, b_in, w_h0, b_h0, w_h1, b_h1,
                                     w_out, b_out, (const unsigned int*)tables);

    void* g_addr = nullptr;
    cudaGetSymbolAddress(&g_addr, g_bias);
    cudaMemcpyToSymbolAsync(c_bias, g_addr, B_TOTAL * sizeof(float), 0,
                            cudaMemcpyDeviceToDevice);

    encode_kernel<<<n / TPB, TPB>>>(coords, tables);

    cudaFuncSetAttribute(mlp_kernel,
                         cudaFuncAttributeMaxDynamicSharedMemorySize, SMEM_TOTAL);
    mlp_kernel<<<n / TPB, TPB, SMEM_TOTAL>>>(out);
}

// round 16
// speedup vs baseline: 1.5505x; 1.0014x over previous
#include <cuda_runtime.h>
#include <cuda_fp16.h>
#include <cstdint>

// ----------------------------------------------------------------------------
// InstantNGP hash encode + 32->64->64->64->16 MLP, split into two kernels:
//  1) encode_kernel: no smem, high occupancy, writes scaled hi/lo fp16
//     feature words to a transposed global buffer (coalesced).
//  2) mlp_kernel: HMMA (m16n8k16) dual-fp16 3-term layers per 32-point warp
//     tile, loading features coalesced from the buffer. Biases via __ldg
//     (no constant-bank memcpy node).
//  prep vectorized: one thread writes a full 16B swizzle atom (8 k-values).
// ----------------------------------------------------------------------------

#define NUM_LEVEL 16
#define LOG_T 19
#define TABLE_SIZE (1u << LOG_T)
#define TABLE_MASK (TABLE_SIZE - 1u)

#define TPB 256
#define NMAX 262144                  // fixed problem size

#define ACT_SCALE   4096.0f          // 2^12
#define ACT_DESCALE (1.0f / 4096.0f)

// ---- bias layout (floats) ----
#define OFF_BIN   0
#define OFF_BH0   64
#define OFF_BH1   128
#define OFF_BOUT  192
#define B_TOTAL   208

__device__ __align__(16) float g_bias[B_TOTAL];
__device__ int   g_tab_mode;       // 0 = half2, 1 = float2, 2 = bf16x2

// Feature buffer: [q][point], q = feature-pair index (0..15).
// .x = hi fp16x2 word, .y = lo fp16x2 word (activations pre-scaled by 2^12).
__device__ __align__(16) uint2 g_feat[16 * NMAX];

// ---- dual-half swizzled B tiles in global (filled by prep) ----
#define BT_B1HI 0
#define BT_B1LO 4096
#define BT_B2HI 8192
#define BT_B2LO 16384
#define BT_B3HI 24576
#define BT_B3LO 32768
#define BT_B4HI 40960
#define BT_B4LO 43008
#define BT_TOTAL 45056

__device__ __align__(16) char g_Btiles[BT_TOTAL];

// ---- MLP kernel SMEM map: per-warp A slabs then B tiles ----
#define SMEM_A     0                  // 8 warps x (AHI 4096 + ALO 4096)
#define WARP_SLAB  8192
#define SMEM_BT    65536
#define SMEM_TOTAL 110592

// ============================================================ helpers
__device__ __forceinline__ uint32_t smem_u32(const void* p) {
    uint32_t a;
    asm("{ .reg .u64 t; cvta.to.shared.u64 t, %1; cvt.u32.u64 %0, t; }"
        : "=r"(a) : "l"(p));
    return a;
}
__device__ __forceinline__ uint32_t sw128(uint32_t off) {   // 128B-pitch rows
    return off ^ ((off >> 3) & 0x70);
}
__device__ __forceinline__ uint32_t sw64(uint32_t off) {    // 64B-pitch rows
    return off ^ ((off >> 2) & 0x30);
}
__device__ __forceinline__ void ldsm_x4(uint32_t* r, uint32_t a) {
    asm volatile("ldmatrix.sync.aligned.m8n8.x4.shared.b16 {%0,%1,%2,%3}, [%4];"
                 : "=r"(r[0]), "=r"(r[1]), "=r"(r[2]), "=r"(r[3]) : "r"(a));
}
__device__ __forceinline__ void ldsm_x2(uint32_t* r, uint32_t a) {
    asm volatile("ldmatrix.sync.aligned.m8n8.x2.shared.b16 {%0,%1}, [%2];"
                 : "=r"(r[0]), "=r"(r[1]) : "r"(a));
}
__device__ __forceinline__ void mma16816(float* c, const uint32_t* a,
                                         const uint32_t* b) {
    asm volatile(
        "mma.sync.aligned.m16n8k16.row.col.f32.f16.f16.f32 "
        "{%0,%1,%2,%3}, {%4,%5,%6,%7}, {%8,%9}, {%0,%1,%2,%3};"
        : "+f"(c[0]), "+f"(c[1]), "+f"(c[2]), "+f"(c[3])
        : "r"(a[0]), "r"(a[1]), "r"(a[2]), "r"(a[3]), "r"(b[0]), "r"(b[1]));
}
__device__ __forceinline__ void sts32(uint32_t a, uint32_t v) {
    asm volatile("st.shared.b32 [%0], %1;" :: "r"(a), "r"(v) : "memory");
}
__device__ __forceinline__ void sts128(uint32_t a, uint4 v) {
    asm volatile("st.shared.v4.b32 [%0], {%1,%2,%3,%4};"
                 :: "r"(a), "r"(v.x), "r"(v.y), "r"(v.z), "r"(v.w) : "memory");
}
__device__ __forceinline__ uint32_t pack_hilo(float v0, float v1, uint32_t& lo_out) {
    __half h0 = __float2half_rn(v0);
    __half h1 = __float2half_rn(v1);
    __half l0 = __float2half_rn(v0 - __half2float(h0));
    __half l1 = __float2half_rn(v1 - __half2float(h1));
    __half2 hp = __halves2half2(h0, h1);
    __half2 lp = __halves2half2(l0, l1);
    lo_out = *(uint32_t*)&lp;
    return *(uint32_t*)&hp;
}

// ------------------------------------------------- prep (+ probe + B tiles)
// Vectorized: one thread emits a full 16B swizzle atom (8 consecutive k) as
// one hi uint4 + one lo uint4.
__device__ __forceinline__ void fill_chunk(const float* __restrict__ w,
                                           int K, int n, int kc,
                                           int bhi, int blo, uint32_t sw) {
    uint32_t hi[4], lo[4];
#pragma unroll
    for (int j = 0; j < 4; j++) {
        float v0 = w[n * K + kc * 8 + 2 * j];
        float v1 = w[n * K + kc * 8 + 2 * j + 1];
        hi[j] = pack_hilo(v0, v1, lo[j]);
    }
    *(uint4*)(g_Btiles + bhi + sw) = make_uint4(hi[0], hi[1], hi[2], hi[3]);
    *(uint4*)(g_Btiles + blo + sw) = make_uint4(lo[0], lo[1], lo[2], lo[3]);
}

__global__ void prep_weights_kernel(
    const float* __restrict__ w_in, const float* __restrict__ b_in,
    const float* __restrict__ w_h0, const float* __restrict__ b_h0,
    const float* __restrict__ w_h1, const float* __restrict__ b_h1,
    const float* __restrict__ w_out, const float* __restrict__ b_out,
    const unsigned int* __restrict__ tab) {
    int t = blockIdx.x * blockDim.x + threadIdx.x;
    int stride = gridDim.x * blockDim.x;

    if (blockIdx.x == 0 && threadIdx.x < 32) {
        int tiny = 0, lowband = 0;
#pragma unroll
        for (int i = 0; i < 8; i++) {
            unsigned int w = __ldg(&tab[(threadIdx.x * 8 + i) * 97 + 1]);
            float fh = __uint_as_float(w);
            float fl = __uint_as_float(w << 16);
            if (fabsf(fh) < 1e-20f) tiny++;
            float al = fabsf(fl);
            if (al > 1e-6f && al < 1e-2f) lowband++;
        }
        tiny    = __reduce_add_sync(0xFFFFFFFFu, tiny);
        lowband = __reduce_add_sync(0xFFFFFFFFu, lowband);
        if (threadIdx.x == 0)
            g_tab_mode = (tiny > 128) ? 0 : ((lowband > 128) ? 2 : 1);
    }

    for (int k = t; k < 64; k += stride) g_bias[OFF_BIN + k] = b_in[k];
    for (int k = t; k < 64; k += stride) g_bias[OFF_BH0 + k] = b_h0[k];
    for (int k = t; k < 64; k += stride) g_bias[OFF_BH1 + k] = b_h1[k];
    for (int k = t; k < 16; k += stride) g_bias[OFF_BOUT + k] = b_out[k];

    // layer1 [64n][32k], 64B pitch, SW64: 64 rows x 4 chunks
    for (int i = t; i < 64 * 4; i += stride) {
        int n = i >> 2, kc = i & 3;
        fill_chunk(w_in, 32, n, kc, BT_B1HI, BT_B1LO,
                   sw64((uint32_t)(n * 64 + kc * 16)));
    }
    // h0 [64n][64k], 128B pitch: 64 rows x 8 chunks
    for (int i = t; i < 64 * 8; i += stride) {
        int n = i >> 3, kc = i & 7;
        fill_chunk(w_h0, 64, n, kc, BT_B2HI, BT_B2LO,
                   sw128((uint32_t)(n * 128 + kc * 16)));
    }
    // h1 [64n][64k]
    for (int i = t; i < 64 * 8; i += stride) {
        int n = i >> 3, kc = i & 7;
        fill_chunk(w_h1, 64, n, kc, BT_B3HI, BT_B3LO,
                   sw128((uint32_t)(n * 128 + kc * 16)));
    }
    // out [16n][64k]
    for (int i = t; i < 16 * 8; i += stride) {
        int n = i >> 3, kc = i & 7;
        fill_chunk(w_out, 64, n, kc, BT_B4HI, BT_B4LO,
                   sw128((uint32_t)(n * 128 + kc * 16)));
    }
}

// ---------------------------------------------------------------- table fetch
template <int MODE>
__device__ __forceinline__ float2 tab_fetch(const void* __restrict__ base,
                                            unsigned idx) {
    if (MODE == 0) {
        __half2 v = __ldg(((const __half2*)base) + idx);
        return __half22float2(v);
    } else if (MODE == 1) {
        return __ldg(((const float2*)base) + idx);
    } else {
        unsigned int w = __ldg(((const unsigned int*)base) + idx);
        return make_float2(__uint_as_float(w << 16),
                           __uint_as_float(w & 0xFFFF0000u));
    }
}

struct LevelSetup {
    unsigned hx0, hx1, hy0, hy1, hz0, hz1;
    float ax, ay, az, bx, by, bz;
};
__device__ __forceinline__ LevelSetup level_setup(float cx, float cy, float cz,
                                                  float r) {
    LevelSetup s;
    float sx = cx * r, sy = cy * r, sz = cz * r;
    float fx = floorf(sx), fy = floorf(sy), fz = floorf(sz);
    float gx = ceilf(sx), gy = ceilf(sy), gz = ceilf(sz);
    s.ax = sx - fx; s.ay = sy - fy; s.az = sz - fz;
    s.bx = gx - sx; s.by = gy - sy; s.bz = gz - sz;
    s.hx0 = (unsigned)(int)fx;
    s.hx1 = (unsigned)(int)gx;
    s.hy0 = (unsigned)(int)fy * 2654435761u;
    s.hy1 = (unsigned)(int)gy * 2654435761u;
    s.hz0 = (unsigned)(int)fz * 805459861u;
    s.hz1 = (unsigned)(int)gz * 805459861u;
    return s;
}
__device__ __forceinline__ unsigned corner_hash(const LevelSetup& s, int o) {
    return (((o & 4) ? s.hx1 : s.hx0) ^ ((o & 2) ? s.hy1 : s.hy0) ^
            ((o & 1) ? s.hz1 : s.hz0)) & TABLE_MASK;
}
__device__ __forceinline__ float corner_w(const LevelSetup& s, int o) {
    return ((o & 4) ? s.ax : s.bx) * ((o & 2) ? s.ay : s.by) *
           ((o & 1) ? s.az : s.bz);
}

// ======================================================= KERNEL 1: encode
template <int MODE>
__device__ __forceinline__ void encode_point(
    const char* __restrict__ tables, float cx, float cy, float cz, int p) {
    const float RES[NUM_LEVEL] = {16.f, 20.f, 25.f, 32.f, 40.f, 50.f, 64.f, 80.f,
                                  101.f, 128.f, 161.f, 203.f, 256.f, 322.f, 406.f, 512.f};
    const int ELEM_BYTES = (MODE == 1) ? 8 : 4;

#pragma unroll
    for (int lp = 0; lp < 8; lp++) {            // 2 levels per batch
        int l0 = 2 * lp, l1 = 2 * lp + 1;
        LevelSetup s0 = level_setup(cx, cy, cz, RES[l0]);
        LevelSetup s1 = level_setup(cx, cy, cz, RES[l1]);
        const void* t0 = tables + (size_t)l0 * TABLE_SIZE * ELEM_BYTES;
        const void* t1 = tables + (size_t)l1 * TABLE_SIZE * ELEM_BYTES;

        float2 f0[8], f1[8];                    // 16 gathers in flight
#pragma unroll
        for (int o = 0; o < 8; o++) f0[o] = tab_fetch<MODE>(t0, corner_hash(s0, o));
#pragma unroll
        for (int o = 0; o < 8; o++) f1[o] = tab_fetch<MODE>(t1, corner_hash(s1, o));

        float a0 = 0.f, a1 = 0.f, b0 = 0.f, b1 = 0.f;
#pragma unroll
        for (int o = 0; o < 8; o++) {
            float w0 = corner_w(s0, o), w1 = corner_w(s1, o);
            a0 = fmaf(f0[o].x, w0, a0);
            a1 = fmaf(f0[o].y, w0, a1);
            b0 = fmaf(f1[o].x, w1, b0);
            b1 = fmaf(f1[o].y, w1, b1);
        }
        uint32_t lo0, hi0 = pack_hilo(a0 * ACT_SCALE, a1 * ACT_SCALE, lo0);
        uint32_t lo1, hi1 = pack_hilo(b0 * ACT_SCALE, b1 * ACT_SCALE, lo1);
        g_feat[l0 * NMAX + p] = make_uint2(hi0, lo0);   // coalesced STG.64
        g_feat[l1 * NMAX + p] = make_uint2(hi1, lo1);
    }
}

__global__ __launch_bounds__(TPB, 3) void encode_kernel(
    const float* __restrict__ coords,
    const char* __restrict__ tables) {
    int p = blockIdx.x * TPB + threadIdx.x;
    float cx = coords[3 * p + 0];
    float cy = coords[3 * p + 1];
    float cz = coords[3 * p + 2];
    int mode = g_tab_mode;
    if (mode == 1)      encode_point<1>(tables, cx, cy, cz, p);
    else if (mode == 0) encode_point<0>(tables, cx, cy, cz, p);
    else                encode_point<2>(tables, cx, cy, cz, p);
}

// ======================================================= KERNEL 2: MLP
template <int KSTEPS, int NTILES, bool B64>
__device__ __forceinline__ void run_layer(
    uint32_t slab_hi, uint32_t slab_lo, uint32_t b_hi, uint32_t b_lo,
    int lane, float acc[2][8][4]) {
#pragma unroll
    for (int mt = 0; mt < 2; mt++)
#pragma unroll
        for (int nt = 0; nt < NTILES; nt++)
#pragma unroll
            for (int i = 0; i < 4; i++) acc[mt][nt][i] = 0.0f;

    uint32_t rA = (uint32_t)(lane & 15);
    uint32_t cA = (uint32_t)((lane >> 4) << 4);
    uint32_t rB = (uint32_t)(lane & 7);
    uint32_t cB = (uint32_t)(((lane >> 3) & 1) << 4);

#pragma unroll
    for (int ks = 0; ks < KSTEPS; ks++) {
        uint32_t ah[2][4], al[2][4];
#pragma unroll
        for (int mt = 0; mt < 2; mt++) {
            uint32_t off = sw128((mt * 16 + rA) * 128 + ks * 32 + cA);
            ldsm_x4(ah[mt], slab_hi + off);
            ldsm_x4(al[mt], slab_lo + off);
        }
#pragma unroll
        for (int nt = 0; nt < NTILES; nt++) {
            uint32_t offB = B64 ? sw64((nt * 8 + rB) * 64 + ks * 32 + cB)
                                : sw128((nt * 8 + rB) * 128 + ks * 32 + cB);
            uint32_t bh[2], bl[2];
            ldsm_x2(bh, b_hi + offB);
            ldsm_x2(bl, b_lo + offB);
#pragma unroll
            for (int mt = 0; mt < 2; mt++) {
                mma16816(acc[mt][nt], ah[mt], bh);
                mma16816(acc[mt][nt], al[mt], bh);
                mma16816(acc[mt][nt], ah[mt], bl);
            }
        }
    }
}

template <int BOFF>
__device__ __forceinline__ void epi_hidden(float acc[2][8][4],
                                           uint32_t slab_hi, uint32_t slab_lo,
                                           int lane) {
    int g = lane >> 2, id = lane & 3;
    __syncwarp();
#pragma unroll
    for (int mt = 0; mt < 2; mt++)
#pragma unroll
        for (int nt = 0; nt < 8; nt++)
#pragma unroll
            for (int h = 0; h < 2; h++) {
                int col = nt * 8 + 2 * id;
                float b0v = __ldg(&g_bias[BOFF + col]);
                float b1v = __ldg(&g_bias[BOFF + col + 1]);
                float v0 = fmaxf(fmaf(acc[mt][nt][2*h],     ACT_DESCALE, b0v), 0.0f);
                float v1 = fmaxf(fmaf(acc[mt][nt][2*h + 1], ACT_DESCALE, b1v), 0.0f);
                uint32_t lo, hi = pack_hilo(v0 * ACT_SCALE, v1 * ACT_SCALE, lo);
                uint32_t off = sw128((mt * 16 + g + 8 * h) * 128 + col * 2);
                sts32(slab_hi + off, hi);
                sts32(slab_lo + off, lo);
            }
    __syncwarp();
}

__global__ __launch_bounds__(TPB, 2) void mlp_kernel(float* __restrict__ out) {
    extern __shared__ char sm[];
    uint32_t smem_base = smem_u32(sm);
    int tid = threadIdx.x;
    int w = tid >> 5;
    int lane = tid & 31;

    // Cooperative B-tile load (only block-wide sync in the kernel)
    {
        const uint4* src = (const uint4*)g_Btiles;
        uint4* dst = (uint4*)(sm + SMEM_BT);
        for (int k = tid; k < BT_TOTAL / 16; k += TPB) dst[k] = src[k];
    }
    __syncthreads();

    uint32_t slab_hi = smem_base + SMEM_A + w * WARP_SLAB;
    uint32_t slab_lo = slab_hi + 4096;
    uint32_t bt = smem_base + SMEM_BT;

    // Load this point's 16 feature-pair words (coalesced LDG.64) into A slab.
    int p = blockIdx.x * TPB + tid;
#pragma unroll
    for (int j = 0; j < 4; j++) {
        uint2 v0 = g_feat[(4 * j + 0) * NMAX + p];
        uint2 v1 = g_feat[(4 * j + 1) * NMAX + p];
        uint2 v2 = g_feat[(4 * j + 2) * NMAX + p];
        uint2 v3 = g_feat[(4 * j + 3) * NMAX + p];
        uint32_t sw = sw128((uint32_t)(lane * 128 + j * 16));
        sts128(slab_hi + sw, make_uint4(v0.x, v1.x, v2.x, v3.x));
        sts128(slab_lo + sw, make_uint4(v0.y, v1.y, v2.y, v3.y));
    }
    __syncwarp();

    float acc[2][8][4];

    // layer 1: K=32 (2 ksteps), N=64, B at 64B pitch
    run_layer<2, 8, true>(slab_hi, slab_lo, bt + BT_B1HI, bt + BT_B1LO, lane, acc);
    epi_hidden<OFF_BIN>(acc, slab_hi, slab_lo, lane);

    // h0: K=64, N=64
    run_layer<4, 8, false>(slab_hi, slab_lo, bt + BT_B2HI, bt + BT_B2LO, lane, acc);
    epi_hidden<OFF_BH0>(acc, slab_hi, slab_lo, lane);

    // h1: K=64, N=64
    run_layer<4, 8, false>(slab_hi, slab_lo, bt + BT_B3HI, bt + BT_B3LO, lane, acc);
    epi_hidden<OFF_BH1>(acc, slab_hi, slab_lo, lane);

    // out: K=64, N=16 (2 ntiles), descale + bias, straight to global
    run_layer<4, 2, false>(slab_hi, slab_lo, bt + BT_B4HI, bt + BT_B4LO, lane, acc);
    {
        int g = lane >> 2, id = lane & 3;
        int pbase = blockIdx.x * TPB + w * 32;
#pragma unroll
        for (int mt = 0; mt < 2; mt++)
#pragma unroll
            for (int nt = 0; nt < 2; nt++)
#pragma unroll
                for (int h = 0; h < 2; h++) {
                    int col = nt * 8 + 2 * id;
                    int row = mt * 16 + g + 8 * h;
                    float b0v = __ldg(&g_bias[OFF_BOUT + col]);
                    float b1v = __ldg(&g_bias[OFF_BOUT + col + 1]);
                    float v0 = fmaf(acc[mt][nt][2*h],     ACT_DESCALE, b0v);
                    float v1 = fmaf(acc[mt][nt][2*h + 1], ACT_DESCALE, b1v);
                    *(float2*)(out + (size_t)(pbase + row) * 16 + col) =
                        make_float2(v0, v1);
                }
    }
}

// ---------------------------------------------------------------- launch
extern "C" void kernel_launch(void* const* d_in, const int* in_sizes, int n_in,
                              void* d_out, int out_size) {
    const float* coords = (const float*)d_in[0];
    const char* tables  = (const char*)d_in[1];
    const float* w_in  = (const float*)d_in[2];
    const float* b_in  = (const float*)d_in[3];
    const float* w_h0  = (const float*)d_in[4];
    const float* b_h0  = (const float*)d_in[5];
    const float* w_h1  = (const float*)d_in[6];
    const float* b_h1  = (const float*)d_in[7];
    const float* w_out = (const float*)d_in[8];
    const float* b_out = (const float*)d_in[9];
    float* out = (float*)d_out;

    int n = in_sizes[0] / 3;

    prep_weights_kernel<<<64, 256>>>(w_in, b_in, w_h0, b_h0, w_h1, b_h1,
                                     w_out, b_out, (const unsigned int*)tables);

    encode_kernel<<<n / TPB, TPB>>>(coords, tables);

    cudaFuncSetAttribute(mlp_kernel,
                         cudaFuncAttributeMaxDynamicSharedMemorySize, SMEM_TOTAL);
    mlp_kernel<<<n / TPB, TPB, SMEM_TOTAL>>>(out);
}